// round 1
// baseline (speedup 1.0000x reference)
#include <cuda_runtime.h>

// LearnableDemosaick: B=8, H=W=1024, K=8 filters of 5x5, edge-clamp padding.
// Only non-green sites (x%2 != y%2) need the conv banks + softmax; green sites
// are a passthrough copy. Each thread computes 4 compute-pixels along x
// (stride 2) and copies the 4 interleaved green pixels.
//
// Mapping: warp lanes run along y (32 rows per warp); smem tile row stride is
// 69 floats (odd, gcd(69 mod 32, 32)=1) so per-tap pixel LDS across lanes is
// (near) bank-conflict free. Filter coefficients live in smem laid out as
// [tap][16] so all 16 channel coefficients of a tap are a 64B-aligned run
// (broadcast LDS across the warp).

#define H_IMG 1024
#define W_IMG 1024
#define TS 69            // smem tile row stride (floats)
#define TILE_ROWS 36     // 32 output rows + 4 halo
#define TILE_COLS 68     // 64 output cols + 4 halo

__global__ __launch_bounds__(256, 2)
void demosaick_kernel(const float* __restrict__ img,
                      const float* __restrict__ selF,
                      const float* __restrict__ grnF,
                      float* __restrict__ out)
{
    __shared__ float tile[TILE_ROWS * TS];
    __shared__ float fco[25 * 16];   // [tap][0..7]=sel, [tap][8..15]=green

    const int b  = blockIdx.z;
    const int y0 = blockIdx.y * 32;
    const int x0 = blockIdx.x * 64;
    const int tid = threadIdx.y * 32 + threadIdx.x;

    // Load + transpose filters into [tap][channel] layout.
    for (int i = tid; i < 400; i += 256) {
        int t = i >> 4, k = i & 15;
        fco[i] = (k < 8) ? selF[k * 25 + t] : grnF[(k - 8) * 25 + t];
    }

    // Load padded image tile with edge clamp.
    const float* imgB = img + (size_t)b * (H_IMG * W_IMG);
    for (int i = tid; i < TILE_ROWS * TILE_COLS; i += 256) {
        int r = i / TILE_COLS, c = i - r * TILE_COLS;
        int gy = y0 - 2 + r; gy = min(max(gy, 0), H_IMG - 1);
        int gx = x0 - 2 + c; gx = min(max(gx, 0), W_IMG - 1);
        tile[r * TS + c] = imgB[gy * W_IMG + gx];
    }
    __syncthreads();

    const int ly = threadIdx.x;            // row within tile (lane)
    const int y  = y0 + ly;
    const int cpar = (y + 1) & 1;          // parity of compute-x for this row
    const int tcc = threadIdx.y * 8 + cpar; // tile col: window col = tcc + dx + 2*i

    float sA[8][4], gA[8][4];
    #pragma unroll
    for (int k = 0; k < 8; k++)
        #pragma unroll
        for (int i = 0; i < 4; i++) { sA[k][i] = 0.0f; gA[k][i] = 0.0f; }

    #pragma unroll
    for (int dy = 0; dy < 5; dy++) {
        const float* rbase = &tile[(ly + dy) * TS + tcc];
        #pragma unroll
        for (int dx = 0; dx < 5; dx++) {
            const float v0 = rbase[dx + 0];
            const float v1 = rbase[dx + 2];
            const float v2 = rbase[dx + 4];
            const float v3 = rbase[dx + 6];
            const float* fc = &fco[(dy * 5 + dx) * 16];
            #pragma unroll
            for (int k = 0; k < 8; k++) {
                const float cs = fc[k];
                const float cg = fc[8 + k];
                sA[k][0] = fmaf(cs, v0, sA[k][0]);
                sA[k][1] = fmaf(cs, v1, sA[k][1]);
                sA[k][2] = fmaf(cs, v2, sA[k][2]);
                sA[k][3] = fmaf(cs, v3, sA[k][3]);
                gA[k][0] = fmaf(cg, v0, gA[k][0]);
                gA[k][1] = fmaf(cg, v1, gA[k][1]);
                gA[k][2] = fmaf(cg, v2, gA[k][2]);
                gA[k][3] = fmaf(cg, v3, gA[k][3]);
            }
        }
    }

    const size_t orow = ((size_t)b * H_IMG + y) * W_IMG + x0;

    // Softmax-blended green estimate at the 4 compute sites.
    #pragma unroll
    for (int i = 0; i < 4; i++) {
        float m = sA[0][i];
        #pragma unroll
        for (int k = 1; k < 8; k++) m = fmaxf(m, sA[k][i]);
        float wsum = 0.0f, gh = 0.0f;
        #pragma unroll
        for (int k = 0; k < 8; k++) {
            float e = __expf(sA[k][i] - m);
            wsum += e;
            gh = fmaf(e, gA[k][i], gh);
        }
        gh = gh / wsum;
        out[orow + threadIdx.y * 8 + cpar + 2 * i] = gh;
    }

    // Passthrough copies at the 4 green sites.
    const int gpar = y & 1;
    #pragma unroll
    for (int i = 0; i < 4; i++) {
        int c = threadIdx.y * 8 + gpar + 2 * i;
        out[orow + c] = tile[(ly + 2) * TS + c + 2];
    }
}

extern "C" void kernel_launch(void* const* d_in, const int* in_sizes, int n_in,
                              void* d_out, int out_size) {
    const float* img  = (const float*)d_in[0];
    const float* selF = (const float*)d_in[1];
    const float* grnF = (const float*)d_in[2];
    float* out = (float*)d_out;
    int B = in_sizes[0] / (H_IMG * W_IMG);
    dim3 grid(W_IMG / 64, H_IMG / 32, B);
    dim3 block(32, 8);
    demosaick_kernel<<<grid, block>>>(img, selF, grnF, out);
}

// round 3
// speedup vs baseline: 1.6115x; 1.6115x over previous
#include <cuda_runtime.h>
#include <cstdint>

// LearnableDemosaick: B=8, H=W=1024, K=8 filters of 5x5, edge-clamp padding.
// Only non-green sites (x%2 != y%2) need the conv banks + softmax; green sites
// are a passthrough copy. Each thread computes 4 compute-pixels along x
// (stride 2) and copies the 4 interleaved green pixels.
//
// Round 2: packed fma.rn.f32x2 — accumulator pairs {sel, green} per (k,pixel),
// coefficient pairs {cs, cg} pre-packed in smem (one LDS.64, warp-broadcast),
// pixel value duplicated {v,v} with one mov.b64. Cuts main-loop issued
// instructions from ~2100 to ~1200 per thread.

#define H_IMG 1024
#define W_IMG 1024
#define TS 69            // smem tile row stride (floats); odd -> conflict-free lane-y
#define TILE_ROWS 36     // 32 output rows + 4 halo
#define TILE_COLS 68     // 64 output cols + 4 halo

typedef unsigned long long u64;

__device__ __forceinline__ u64 fma2(u64 a, u64 b, u64 c) {
    u64 d;
    asm("fma.rn.f32x2 %0, %1, %2, %3;" : "=l"(d) : "l"(a), "l"(b), "l"(c));
    return d;
}
__device__ __forceinline__ u64 dup2(float v) {
    u64 d;
    asm("mov.b64 %0, {%1, %1};" : "=l"(d) : "f"(v));
    return d;
}
__device__ __forceinline__ void unpack2(u64 p, float& lo, float& hi) {
    asm("mov.b64 {%0, %1}, %2;" : "=f"(lo), "=f"(hi) : "l"(p));
}

__global__ __launch_bounds__(256, 2)
void demosaick_kernel(const float* __restrict__ img,
                      const float* __restrict__ selF,
                      const float* __restrict__ grnF,
                      float* __restrict__ out)
{
    __shared__ float tile[TILE_ROWS * TS];
    __shared__ float2 fco2[25 * 8];   // [tap][k] = {sel coeff, green coeff}

    const int b  = blockIdx.z;
    const int y0 = blockIdx.y * 32;
    const int x0 = blockIdx.x * 64;
    const int tid = threadIdx.y * 32 + threadIdx.x;

    // Load + transpose filters into [tap][k] = {cs, cg} pairs.
    for (int i = tid; i < 200; i += 256) {
        int t = i >> 3, k = i & 7;
        fco2[i] = make_float2(selF[k * 25 + t], grnF[k * 25 + t]);
    }

    // Load padded image tile with edge clamp.
    const float* imgB = img + (size_t)b * (H_IMG * W_IMG);
    for (int i = tid; i < TILE_ROWS * TILE_COLS; i += 256) {
        int r = i / TILE_COLS, c = i - r * TILE_COLS;
        int gy = y0 - 2 + r; gy = min(max(gy, 0), H_IMG - 1);
        int gx = x0 - 2 + c; gx = min(max(gx, 0), W_IMG - 1);
        tile[r * TS + c] = imgB[gy * W_IMG + gx];
    }
    __syncthreads();

    const int ly = threadIdx.x;             // row within tile (lane)
    const int y  = y0 + ly;
    const int cpar = (y + 1) & 1;           // parity of compute-x for this row
    const int tcc = threadIdx.y * 8 + cpar; // window col = tcc + dx + 2*i

    // acc[k][i] = { sel_accum, green_accum } for filter k, compute pixel i
    u64 acc[8][4];
    #pragma unroll
    for (int k = 0; k < 8; k++)
        #pragma unroll
        for (int i = 0; i < 4; i++) acc[k][i] = 0ULL;

    #pragma unroll
    for (int dy = 0; dy < 5; dy++) {
        const float* rbase = &tile[(ly + dy) * TS + tcc];
        #pragma unroll
        for (int dx = 0; dx < 5; dx++) {
            const u64 v0 = dup2(rbase[dx + 0]);
            const u64 v1 = dup2(rbase[dx + 2]);
            const u64 v2 = dup2(rbase[dx + 4]);
            const u64 v3 = dup2(rbase[dx + 6]);
            const u64* fc = reinterpret_cast<const u64*>(&fco2[(dy * 5 + dx) * 8]);
            #pragma unroll
            for (int k = 0; k < 8; k++) {
                const u64 c = fc[k];   // one LDS.64, broadcast
                acc[k][0] = fma2(c, v0, acc[k][0]);
                acc[k][1] = fma2(c, v1, acc[k][1]);
                acc[k][2] = fma2(c, v2, acc[k][2]);
                acc[k][3] = fma2(c, v3, acc[k][3]);
            }
        }
    }

    const size_t orow = ((size_t)b * H_IMG + y) * W_IMG + x0;

    // Softmax-blended green estimate at the 4 compute sites.
    #pragma unroll
    for (int i = 0; i < 4; i++) {
        float s[8], g[8];
        #pragma unroll
        for (int k = 0; k < 8; k++) unpack2(acc[k][i], s[k], g[k]);
        float m = s[0];
        #pragma unroll
        for (int k = 1; k < 8; k++) m = fmaxf(m, s[k]);
        float wsum = 0.0f, gh = 0.0f;
        #pragma unroll
        for (int k = 0; k < 8; k++) {
            float e = __expf(s[k] - m);
            wsum += e;
            gh = fmaf(e, g[k], gh);
        }
        gh = gh / wsum;
        out[orow + threadIdx.y * 8 + cpar + 2 * i] = gh;
    }

    // Passthrough copies at the 4 green sites.
    const int gpar = y & 1;
    #pragma unroll
    for (int i = 0; i < 4; i++) {
        int c = threadIdx.y * 8 + gpar + 2 * i;
        out[orow + c] = tile[(ly + 2) * TS + c + 2];
    }
}

extern "C" void kernel_launch(void* const* d_in, const int* in_sizes, int n_in,
                              void* d_out, int out_size) {
    const float* img  = (const float*)d_in[0];
    const float* selF = (const float*)d_in[1];
    const float* grnF = (const float*)d_in[2];
    float* out = (float*)d_out;
    int B = in_sizes[0] / (H_IMG * W_IMG);
    dim3 grid(W_IMG / 64, H_IMG / 32, B);
    dim3 block(32, 8);
    demosaick_kernel<<<grid, block>>>(img, selF, grnF, out);
}

// round 4
// speedup vs baseline: 1.8315x; 1.1365x over previous
#include <cuda_runtime.h>
#include <cstdint>

// LearnableDemosaick R3:
//  - dup-packed u64 tile {v,v}: LDS.64 yields the packed FMA2 operand (no dup2)
//  - 11 distinct pixel pairs per dy row, loaded once, reused across dx
//  - coefficients as float4 {sel_2j, grn_2j, sel_2j+1, grn_2j+1} -> LDS.128
//  - output staged in smem, stored with coalesced float4 STG (lanes ran along y
//    for compute; naive stores were 32 wavefronts per warp-store)

#define H_IMG 1024
#define W_IMG 1024
#define TS 69            // dup-tile row stride in u64 (lane phase conflict-free)
#define TILE_ROWS 36     // 32 output rows + 4 halo
#define TILE_COLS 68     // 64 output cols + 4 halo
#define SGS 68           // output stage row stride (floats), 16B-aligned rows

typedef unsigned long long u64;

__device__ __forceinline__ u64 fma2(u64 a, u64 b, u64 c) {
    u64 d;
    asm("fma.rn.f32x2 %0, %1, %2, %3;" : "=l"(d) : "l"(a), "l"(b), "l"(c));
    return d;
}
__device__ __forceinline__ u64 dup2(float v) {
    u64 d;
    asm("mov.b64 %0, {%1, %1};" : "=l"(d) : "f"(v));
    return d;
}
__device__ __forceinline__ void unpack2(u64 p, float& lo, float& hi) {
    asm("mov.b64 {%0, %1}, %2;" : "=f"(lo), "=f"(hi) : "l"(p));
}

__global__ __launch_bounds__(256, 2)
void demosaick_kernel(const float* __restrict__ img,
                      const float* __restrict__ selF,
                      const float* __restrict__ grnF,
                      float* __restrict__ out)
{
    __shared__ u64 tile[TILE_ROWS * TS];        // {v,v} per pixel
    __shared__ float4 fco[25 * 4];              // [tap][kpair]
    __shared__ float stage[32 * SGS];           // output tile

    const int b  = blockIdx.z;
    const int y0 = blockIdx.y * 32;
    const int x0 = blockIdx.x * 64;
    const int tid = threadIdx.y * 32 + threadIdx.x;

    // Filters: [tap][j] = {sel_{2j}, grn_{2j}, sel_{2j+1}, grn_{2j+1}}
    for (int i = tid; i < 100; i += 256) {
        int t = i >> 2, j = i & 3;
        fco[i] = make_float4(selF[(2 * j) * 25 + t],     grnF[(2 * j) * 25 + t],
                             selF[(2 * j + 1) * 25 + t], grnF[(2 * j + 1) * 25 + t]);
    }

    // Padded image tile, edge clamp, stored duplicated.
    const float* imgB = img + (size_t)b * (H_IMG * W_IMG);
    for (int i = tid; i < TILE_ROWS * TILE_COLS; i += 256) {
        int r = i / TILE_COLS, c = i - r * TILE_COLS;
        int gy = y0 - 2 + r; gy = min(max(gy, 0), H_IMG - 1);
        int gx = x0 - 2 + c; gx = min(max(gx, 0), W_IMG - 1);
        tile[r * TS + c] = dup2(imgB[gy * W_IMG + gx]);
    }
    __syncthreads();

    const int ly = threadIdx.x;             // tile row (lane along y)
    const int y  = y0 + ly;
    const int cpar = (y + 1) & 1;           // compute-site x parity for this row
    const int tcc = threadIdx.y * 8 + cpar; // window col = tcc + dx + 2*i

    u64 acc[8][4];
    #pragma unroll
    for (int k = 0; k < 8; k++)
        #pragma unroll
        for (int i = 0; i < 4; i++) acc[k][i] = 0ULL;

    #pragma unroll
    for (int dy = 0; dy < 5; dy++) {
        const u64* rb = &tile[(ly + dy) * TS + tcc];
        u64 v[11];
        #pragma unroll
        for (int c = 0; c < 11; c++) v[c] = rb[c];
        #pragma unroll
        for (int dx = 0; dx < 5; dx++) {
            const ulonglong2* fc =
                reinterpret_cast<const ulonglong2*>(&fco[(dy * 5 + dx) * 4]);
            #pragma unroll
            for (int j = 0; j < 4; j++) {
                const ulonglong2 cc = fc[j];   // LDS.128: k=2j and k=2j+1 pairs
                #pragma unroll
                for (int i = 0; i < 4; i++) {
                    acc[2 * j][i]     = fma2(cc.x, v[dx + 2 * i], acc[2 * j][i]);
                    acc[2 * j + 1][i] = fma2(cc.y, v[dx + 2 * i], acc[2 * j + 1][i]);
                }
            }
        }
    }

    // Softmax blend -> stage
    #pragma unroll
    for (int i = 0; i < 4; i++) {
        float s[8], g[8];
        #pragma unroll
        for (int k = 0; k < 8; k++) unpack2(acc[k][i], s[k], g[k]);
        float m = s[0];
        #pragma unroll
        for (int k = 1; k < 8; k++) m = fmaxf(m, s[k]);
        float wsum = 0.0f, gh = 0.0f;
        #pragma unroll
        for (int k = 0; k < 8; k++) {
            float e = __expf(s[k] - m);
            wsum += e;
            gh = fmaf(e, g[k], gh);
        }
        stage[ly * SGS + tcc - cpar + cpar + 2 * i + 0] = gh / wsum; // col = tcc+2i
    }

    // Passthrough green sites -> stage (low half of dup pair)
    const int gpar = y & 1;
    #pragma unroll
    for (int i = 0; i < 4; i++) {
        int c = threadIdx.y * 8 + gpar + 2 * i;
        float lo, hi;
        unpack2(tile[(ly + 2) * TS + c + 2], lo, hi);
        stage[ly * SGS + c] = lo;
    }
    __syncthreads();

    // Coalesced store: 512 float4 per CTA
    #pragma unroll
    for (int f = tid; f < 512; f += 256) {
        int row = f >> 4, c4 = (f & 15) * 4;
        float4 val = *reinterpret_cast<const float4*>(&stage[row * SGS + c4]);
        *reinterpret_cast<float4*>(
            &out[((size_t)b * H_IMG + y0 + row) * W_IMG + x0 + c4]) = val;
    }
}

extern "C" void kernel_launch(void* const* d_in, const int* in_sizes, int n_in,
                              void* d_out, int out_size) {
    const float* img  = (const float*)d_in[0];
    const float* selF = (const float*)d_in[1];
    const float* grnF = (const float*)d_in[2];
    float* out = (float*)d_out;
    int B = in_sizes[0] / (H_IMG * W_IMG);
    dim3 grid(W_IMG / 64, H_IMG / 32, B);
    dim3 block(32, 8);
    demosaick_kernel<<<grid, block>>>(img, selF, grnF, out);
}

// round 11
// speedup vs baseline: 2.0604x; 1.1250x over previous
#include <cuda_runtime.h>
#include <cstdint>

// LearnableDemosaick R10 (= R8 kernel + fixed symbol-memcpy source address):
//  - coefficients in __constant__ memory: prep kernel packs interleaved
//    {sel,grn} u64 pairs into a __device__ scratch; the scratch's REAL device
//    address (cudaGetSymbolAddress) is memcpy'd into the constant bank.
//    Inner-loop coefficient reads are uniform LDC/LDCU with immediate
//    offsets on the const port — zero smem crossbar traffic for coefficients.
//  - dup-packed u64 tile {v,v}: LDS.64 yields the packed FMA2 operand
//  - per-dy: 11 distinct pixel pairs loaded once, reused across dx
//  - softmax without max-subtraction (sel is O(0.1)), __fdividef
//  - output staged in smem, coalesced float4 stores
//
// Coefficient layout (u64 view of c_fco): index tap*8 + k = {sel_k, grn_k}.

#define H_IMG 1024
#define W_IMG 1024
#define TS 69            // dup-tile row stride in u64 (lane phase conflict-free)
#define TILE_ROWS 36
#define TILE_COLS 68
#define SGS 68           // output stage row stride (floats)

typedef unsigned long long u64;

__constant__ u64 c_fco[25 * 8];      // [tap][k] = {sel_k, grn_k}
__device__ u64 d_fco_scratch[25 * 8];

__device__ __forceinline__ u64 fma2(u64 a, u64 b, u64 c) {
    u64 d;
    asm("fma.rn.f32x2 %0, %1, %2, %3;" : "=l"(d) : "l"(a), "l"(b), "l"(c));
    return d;
}
__device__ __forceinline__ u64 dup2(float v) {
    u64 d;
    asm("mov.b64 %0, {%1, %1};" : "=l"(d) : "f"(v));
    return d;
}
__device__ __forceinline__ u64 pack2(float lo, float hi) {
    u64 d;
    asm("mov.b64 %0, {%1, %2};" : "=l"(d) : "f"(lo), "f"(hi));
    return d;
}
__device__ __forceinline__ void unpack2(u64 p, float& lo, float& hi) {
    asm("mov.b64 {%0, %1}, %2;" : "=f"(lo), "=f"(hi) : "l"(p));
}

__global__ void pack_filters(const float* __restrict__ selF,
                             const float* __restrict__ grnF)
{
    int i = threadIdx.x;             // 200 entries
    if (i < 200) {
        int t = i >> 3, k = i & 7;   // tap, filter
        d_fco_scratch[i] = pack2(selF[k * 25 + t], grnF[k * 25 + t]);
    }
}

__global__ __launch_bounds__(256, 2)
void demosaick_kernel(const float* __restrict__ img,
                      float* __restrict__ out)
{
    __shared__ u64 tile[TILE_ROWS * TS];
    __shared__ float stage[32 * SGS];

    const int b  = blockIdx.z;
    const int y0 = blockIdx.y * 32;
    const int x0 = blockIdx.x * 64;
    const int tid = threadIdx.y * 32 + threadIdx.x;

    // Padded image tile, edge clamp, stored duplicated {v,v}.
    const float* imgB = img + (size_t)b * (H_IMG * W_IMG);
    for (int i = tid; i < TILE_ROWS * TILE_COLS; i += 256) {
        int r = i / TILE_COLS, c = i - r * TILE_COLS;
        int gy = y0 - 2 + r; gy = min(max(gy, 0), H_IMG - 1);
        int gx = x0 - 2 + c; gx = min(max(gx, 0), W_IMG - 1);
        tile[r * TS + c] = dup2(imgB[gy * W_IMG + gx]);
    }
    __syncthreads();

    const int ly = threadIdx.x;             // tile row (lane along y)
    const int y  = y0 + ly;
    const int cpar = (y + 1) & 1;           // compute-site x parity
    const int tcc = threadIdx.y * 8 + cpar; // window col = tcc + dx + 2*i

    u64 acc[8][4];
    #pragma unroll
    for (int k = 0; k < 8; k++)
        #pragma unroll
        for (int i = 0; i < 4; i++) acc[k][i] = 0ULL;

    #pragma unroll
    for (int dy = 0; dy < 5; dy++) {
        const u64* rb = &tile[(ly + dy) * TS + tcc];
        u64 v[11];
        #pragma unroll
        for (int c = 0; c < 11; c++) v[c] = rb[c];
        #pragma unroll
        for (int dx = 0; dx < 5; dx++) {
            const int tap = dy * 5 + dx;
            #pragma unroll
            for (int k = 0; k < 8; k++) {
                const u64 cc = c_fco[tap * 8 + k];   // uniform LDC, imm offset
                #pragma unroll
                for (int i = 0; i < 4; i++)
                    acc[k][i] = fma2(cc, v[dx + 2 * i], acc[k][i]);
            }
        }
    }

    // Softmax blend -> stage (no max subtraction: sel values are O(0.1))
    #pragma unroll
    for (int i = 0; i < 4; i++) {
        float s[8], g[8];
        #pragma unroll
        for (int k = 0; k < 8; k++) unpack2(acc[k][i], s[k], g[k]);
        float wsum = 0.0f, gh = 0.0f;
        #pragma unroll
        for (int k = 0; k < 8; k++) {
            float e = __expf(s[k]);
            wsum += e;
            gh = fmaf(e, g[k], gh);
        }
        stage[ly * SGS + tcc + 2 * i] = __fdividef(gh, wsum);
    }

    // Passthrough green sites -> stage (low half of dup pair)
    const int gpar = y & 1;
    #pragma unroll
    for (int i = 0; i < 4; i++) {
        int c = threadIdx.y * 8 + gpar + 2 * i;
        float lo, hi;
        unpack2(tile[(ly + 2) * TS + c + 2], lo, hi);
        stage[ly * SGS + c] = lo;
    }
    __syncthreads();

    // Coalesced store: 512 float4 per CTA
    #pragma unroll
    for (int f = tid; f < 512; f += 256) {
        int row = f >> 4, c4i = (f & 15) * 4;
        float4 val = *reinterpret_cast<const float4*>(&stage[row * SGS + c4i]);
        *reinterpret_cast<float4*>(
            &out[((size_t)b * H_IMG + y0 + row) * W_IMG + x0 + c4i]) = val;
    }
}

extern "C" void kernel_launch(void* const* d_in, const int* in_sizes, int n_in,
                              void* d_out, int out_size) {
    const float* img  = (const float*)d_in[0];
    const float* selF = (const float*)d_in[1];
    const float* grnF = (const float*)d_in[2];
    float* out = (float*)d_out;
    int B = in_sizes[0] / (H_IMG * W_IMG);

    pack_filters<<<1, 256>>>(selF, grnF);

    // The source of a symbol-memcpy must be a REAL device pointer; the raw
    // identifier of a __device__ variable in host code is the shadow symbol
    // (the R4/R8 bug: the copy failed silently and c_fco stayed zero).
    void* scratch_dev = nullptr;
    cudaGetSymbolAddress(&scratch_dev, d_fco_scratch);
    cudaMemcpyToSymbolAsync(c_fco, scratch_dev, sizeof(u64) * 200, 0,
                            cudaMemcpyDeviceToDevice, 0);

    dim3 grid(W_IMG / 64, H_IMG / 32, B);
    dim3 block(32, 8);
    demosaick_kernel<<<grid, block>>>(img, out);
}

// round 14
// speedup vs baseline: 2.3425x; 1.1369x over previous
#include <cuda_runtime.h>
#include <cstdint>

// LearnableDemosaick R11 (= R10 + occupancy push):
//  - dx loop split by parity (even dx uses 6 even-offset pixel pairs, odd dx
//    uses 5 odd-offset pairs) -> live v[] drops 22 -> ~12 regs
//  - __launch_bounds__(256, 3): 3 CTAs/SM (24 warps, 6/SMSP) vs previous 2;
//    FMA2 floor is ~47us, prior run was latency-limited at 4 warps/SMSP
//  - everything else unchanged: const-bank coefficients (uniform LDC),
//    dup-packed {v,v} u64 tile, no-max softmax, staged float4 stores

#define H_IMG 1024
#define W_IMG 1024
#define TS 69            // dup-tile row stride in u64 (lane phase conflict-free)
#define TILE_ROWS 36
#define TILE_COLS 68
#define SGS 68           // output stage row stride (floats)

typedef unsigned long long u64;

__constant__ u64 c_fco[25 * 8];      // [tap][k] = {sel_k, grn_k}
__device__ u64 d_fco_scratch[25 * 8];

__device__ __forceinline__ u64 fma2(u64 a, u64 b, u64 c) {
    u64 d;
    asm("fma.rn.f32x2 %0, %1, %2, %3;" : "=l"(d) : "l"(a), "l"(b), "l"(c));
    return d;
}
__device__ __forceinline__ u64 dup2(float v) {
    u64 d;
    asm("mov.b64 %0, {%1, %1};" : "=l"(d) : "f"(v));
    return d;
}
__device__ __forceinline__ u64 pack2(float lo, float hi) {
    u64 d;
    asm("mov.b64 %0, {%1, %2};" : "=l"(d) : "f"(lo), "f"(hi));
    return d;
}
__device__ __forceinline__ void unpack2(u64 p, float& lo, float& hi) {
    asm("mov.b64 {%0, %1}, %2;" : "=f"(lo), "=f"(hi) : "l"(p));
}

__global__ void pack_filters(const float* __restrict__ selF,
                             const float* __restrict__ grnF)
{
    int i = threadIdx.x;             // 200 entries
    if (i < 200) {
        int t = i >> 3, k = i & 7;   // tap, filter
        d_fco_scratch[i] = pack2(selF[k * 25 + t], grnF[k * 25 + t]);
    }
}

__global__ __launch_bounds__(256, 3)
void demosaick_kernel(const float* __restrict__ img,
                      float* __restrict__ out)
{
    __shared__ u64 tile[TILE_ROWS * TS];
    __shared__ float stage[32 * SGS];

    const int b  = blockIdx.z;
    const int y0 = blockIdx.y * 32;
    const int x0 = blockIdx.x * 64;
    const int tid = threadIdx.y * 32 + threadIdx.x;

    // Padded image tile, edge clamp, stored duplicated {v,v}.
    const float* imgB = img + (size_t)b * (H_IMG * W_IMG);
    for (int i = tid; i < TILE_ROWS * TILE_COLS; i += 256) {
        int r = i / TILE_COLS, c = i - r * TILE_COLS;
        int gy = y0 - 2 + r; gy = min(max(gy, 0), H_IMG - 1);
        int gx = x0 - 2 + c; gx = min(max(gx, 0), W_IMG - 1);
        tile[r * TS + c] = dup2(imgB[gy * W_IMG + gx]);
    }
    __syncthreads();

    const int ly = threadIdx.x;             // tile row (lane along y)
    const int y  = y0 + ly;
    const int cpar = (y + 1) & 1;           // compute-site x parity
    const int tcc = threadIdx.y * 8 + cpar; // window col = tcc + dx + 2*i

    u64 acc[8][4];
    #pragma unroll
    for (int k = 0; k < 8; k++)
        #pragma unroll
        for (int i = 0; i < 4; i++) acc[k][i] = 0ULL;

    #pragma unroll
    for (int dy = 0; dy < 5; dy++) {
        const u64* rb = &tile[(ly + dy) * TS + tcc];

        // even dx taps (0,2,4): offsets dx+2i are even -> 6 pairs
        {
            u64 ve[6];
            #pragma unroll
            for (int c = 0; c < 6; c++) ve[c] = rb[2 * c];
            #pragma unroll
            for (int h = 0; h < 3; h++) {           // dx = 2h
                const int tap = dy * 5 + 2 * h;
                #pragma unroll
                for (int k = 0; k < 8; k++) {
                    const u64 cc = c_fco[tap * 8 + k];
                    #pragma unroll
                    for (int i = 0; i < 4; i++)
                        acc[k][i] = fma2(cc, ve[h + i], acc[k][i]);
                }
            }
        }
        // odd dx taps (1,3): offsets odd -> 5 pairs
        {
            u64 vo[5];
            #pragma unroll
            for (int c = 0; c < 5; c++) vo[c] = rb[2 * c + 1];
            #pragma unroll
            for (int h = 0; h < 2; h++) {           // dx = 2h+1
                const int tap = dy * 5 + 2 * h + 1;
                #pragma unroll
                for (int k = 0; k < 8; k++) {
                    const u64 cc = c_fco[tap * 8 + k];
                    #pragma unroll
                    for (int i = 0; i < 4; i++)
                        acc[k][i] = fma2(cc, vo[h + i], acc[k][i]);
                }
            }
        }
    }

    // Softmax blend -> stage (no max subtraction: sel values are O(0.1))
    #pragma unroll
    for (int i = 0; i < 4; i++) {
        float s[8], g[8];
        #pragma unroll
        for (int k = 0; k < 8; k++) unpack2(acc[k][i], s[k], g[k]);
        float wsum = 0.0f, gh = 0.0f;
        #pragma unroll
        for (int k = 0; k < 8; k++) {
            float e = __expf(s[k]);
            wsum += e;
            gh = fmaf(e, g[k], gh);
        }
        stage[ly * SGS + tcc + 2 * i] = __fdividef(gh, wsum);
    }

    // Passthrough green sites -> stage (low half of dup pair)
    const int gpar = y & 1;
    #pragma unroll
    for (int i = 0; i < 4; i++) {
        int c = threadIdx.y * 8 + gpar + 2 * i;
        float lo, hi;
        unpack2(tile[(ly + 2) * TS + c + 2], lo, hi);
        stage[ly * SGS + c] = lo;
    }
    __syncthreads();

    // Coalesced store: 512 float4 per CTA
    #pragma unroll
    for (int f = tid; f < 512; f += 256) {
        int row = f >> 4, c4i = (f & 15) * 4;
        float4 val = *reinterpret_cast<const float4*>(&stage[row * SGS + c4i]);
        *reinterpret_cast<float4*>(
            &out[((size_t)b * H_IMG + y0 + row) * W_IMG + x0 + c4i]) = val;
    }
}

extern "C" void kernel_launch(void* const* d_in, const int* in_sizes, int n_in,
                              void* d_out, int out_size) {
    const float* img  = (const float*)d_in[0];
    const float* selF = (const float*)d_in[1];
    const float* grnF = (const float*)d_in[2];
    float* out = (float*)d_out;
    int B = in_sizes[0] / (H_IMG * W_IMG);

    pack_filters<<<1, 256>>>(selF, grnF);

    void* scratch_dev = nullptr;
    cudaGetSymbolAddress(&scratch_dev, d_fco_scratch);
    cudaMemcpyToSymbolAsync(c_fco, scratch_dev, sizeof(u64) * 200, 0,
                            cudaMemcpyDeviceToDevice, 0);

    dim3 grid(W_IMG / 64, H_IMG / 32, B);
    dim3 block(32, 8);
    demosaick_kernel<<<grid, block>>>(img, out);
}

// round 15
// speedup vs baseline: 2.3574x; 1.0064x over previous
#include <cuda_runtime.h>
#include <cstdint>

// LearnableDemosaick R14 (= R11 + LDC.128 coefficient loads):
//  - coefficient pairs for adjacent filters k=2j,2j+1 of a tap are contiguous
//    16B-aligned in the constant bank -> load as one ulonglong2 (LDC.128).
//    200 LDC.64 -> 100 LDC.128 per thread. Theory: the half-rate constant
//    port (LDC->LDC floor 8/inst) was co-binding with the FMA2 pipe
//    (6w x 200 x 8 = 9600 cyc/SMSP == 6w x 800 x rt2). Halving LDC issue
//    count leaves the FMA pipe as the sole binder.
//  - everything else identical to R11: 3 CTAs/SM, parity-split dx (low regs),
//    dup-packed {v,v} u64 tile, no-max softmax, staged float4 stores.

#define H_IMG 1024
#define W_IMG 1024
#define TS 69            // dup-tile row stride in u64 (lane phase conflict-free)
#define TILE_ROWS 36
#define TILE_COLS 68
#define SGS 68           // output stage row stride (floats)

typedef unsigned long long u64;

__constant__ u64 c_fco[25 * 8];      // [tap][k] = {sel_k, grn_k}
__device__ u64 d_fco_scratch[25 * 8];

__device__ __forceinline__ u64 fma2(u64 a, u64 b, u64 c) {
    u64 d;
    asm("fma.rn.f32x2 %0, %1, %2, %3;" : "=l"(d) : "l"(a), "l"(b), "l"(c));
    return d;
}
__device__ __forceinline__ u64 dup2(float v) {
    u64 d;
    asm("mov.b64 %0, {%1, %1};" : "=l"(d) : "f"(v));
    return d;
}
__device__ __forceinline__ u64 pack2(float lo, float hi) {
    u64 d;
    asm("mov.b64 %0, {%1, %2};" : "=l"(d) : "f"(lo), "f"(hi));
    return d;
}
__device__ __forceinline__ void unpack2(u64 p, float& lo, float& hi) {
    asm("mov.b64 {%0, %1}, %2;" : "=f"(lo), "=f"(hi) : "l"(p));
}

__global__ void pack_filters(const float* __restrict__ selF,
                             const float* __restrict__ grnF)
{
    int i = threadIdx.x;             // 200 entries
    if (i < 200) {
        int t = i >> 3, k = i & 7;   // tap, filter
        d_fco_scratch[i] = pack2(selF[k * 25 + t], grnF[k * 25 + t]);
    }
}

__global__ __launch_bounds__(256, 3)
void demosaick_kernel(const float* __restrict__ img,
                      float* __restrict__ out)
{
    __shared__ u64 tile[TILE_ROWS * TS];
    __shared__ float stage[32 * SGS];

    const int b  = blockIdx.z;
    const int y0 = blockIdx.y * 32;
    const int x0 = blockIdx.x * 64;
    const int tid = threadIdx.y * 32 + threadIdx.x;

    // Padded image tile, edge clamp, stored duplicated {v,v}.
    const float* imgB = img + (size_t)b * (H_IMG * W_IMG);
    for (int i = tid; i < TILE_ROWS * TILE_COLS; i += 256) {
        int r = i / TILE_COLS, c = i - r * TILE_COLS;
        int gy = y0 - 2 + r; gy = min(max(gy, 0), H_IMG - 1);
        int gx = x0 - 2 + c; gx = min(max(gx, 0), W_IMG - 1);
        tile[r * TS + c] = dup2(imgB[gy * W_IMG + gx]);
    }
    __syncthreads();

    const int ly = threadIdx.x;             // tile row (lane along y)
    const int y  = y0 + ly;
    const int cpar = (y + 1) & 1;           // compute-site x parity
    const int tcc = threadIdx.y * 8 + cpar; // window col = tcc + dx + 2*i

    u64 acc[8][4];
    #pragma unroll
    for (int k = 0; k < 8; k++)
        #pragma unroll
        for (int i = 0; i < 4; i++) acc[k][i] = 0ULL;

    const ulonglong2* fc128 = reinterpret_cast<const ulonglong2*>(c_fco);
    // fc128[tap*4 + j] = { {sel,grn}_{2j}, {sel,grn}_{2j+1} }

    #pragma unroll
    for (int dy = 0; dy < 5; dy++) {
        const u64* rb = &tile[(ly + dy) * TS + tcc];

        // even dx taps (0,2,4): offsets dx+2i are even -> 6 pairs
        {
            u64 ve[6];
            #pragma unroll
            for (int c = 0; c < 6; c++) ve[c] = rb[2 * c];
            #pragma unroll
            for (int h = 0; h < 3; h++) {           // dx = 2h
                const int tap = dy * 5 + 2 * h;
                #pragma unroll
                for (int j = 0; j < 4; j++) {
                    const ulonglong2 cc = fc128[tap * 4 + j];  // LDC.128
                    #pragma unroll
                    for (int i = 0; i < 4; i++) {
                        acc[2 * j][i]     = fma2(cc.x, ve[h + i], acc[2 * j][i]);
                        acc[2 * j + 1][i] = fma2(cc.y, ve[h + i], acc[2 * j + 1][i]);
                    }
                }
            }
        }
        // odd dx taps (1,3): offsets odd -> 5 pairs
        {
            u64 vo[5];
            #pragma unroll
            for (int c = 0; c < 5; c++) vo[c] = rb[2 * c + 1];
            #pragma unroll
            for (int h = 0; h < 2; h++) {           // dx = 2h+1
                const int tap = dy * 5 + 2 * h + 1;
                #pragma unroll
                for (int j = 0; j < 4; j++) {
                    const ulonglong2 cc = fc128[tap * 4 + j];  // LDC.128
                    #pragma unroll
                    for (int i = 0; i < 4; i++) {
                        acc[2 * j][i]     = fma2(cc.x, vo[h + i], acc[2 * j][i]);
                        acc[2 * j + 1][i] = fma2(cc.y, vo[h + i], acc[2 * j + 1][i]);
                    }
                }
            }
        }
    }

    // Softmax blend -> stage (no max subtraction: sel values are O(0.1))
    #pragma unroll
    for (int i = 0; i < 4; i++) {
        float s[8], g[8];
        #pragma unroll
        for (int k = 0; k < 8; k++) unpack2(acc[k][i], s[k], g[k]);
        float wsum = 0.0f, gh = 0.0f;
        #pragma unroll
        for (int k = 0; k < 8; k++) {
            float e = __expf(s[k]);
            wsum += e;
            gh = fmaf(e, g[k], gh);
        }
        stage[ly * SGS + tcc + 2 * i] = __fdividef(gh, wsum);
    }

    // Passthrough green sites -> stage (low half of dup pair)
    const int gpar = y & 1;
    #pragma unroll
    for (int i = 0; i < 4; i++) {
        int c = threadIdx.y * 8 + gpar + 2 * i;
        float lo, hi;
        unpack2(tile[(ly + 2) * TS + c + 2], lo, hi);
        stage[ly * SGS + c] = lo;
    }
    __syncthreads();

    // Coalesced store: 512 float4 per CTA
    #pragma unroll
    for (int f = tid; f < 512; f += 256) {
        int row = f >> 4, c4i = (f & 15) * 4;
        float4 val = *reinterpret_cast<const float4*>(&stage[row * SGS + c4i]);
        *reinterpret_cast<float4*>(
            &out[((size_t)b * H_IMG + y0 + row) * W_IMG + x0 + c4i]) = val;
    }
}

extern "C" void kernel_launch(void* const* d_in, const int* in_sizes, int n_in,
                              void* d_out, int out_size) {
    const float* img  = (const float*)d_in[0];
    const float* selF = (const float*)d_in[1];
    const float* grnF = (const float*)d_in[2];
    float* out = (float*)d_out;
    int B = in_sizes[0] / (H_IMG * W_IMG);

    pack_filters<<<1, 256>>>(selF, grnF);

    void* scratch_dev = nullptr;
    cudaGetSymbolAddress(&scratch_dev, d_fco_scratch);
    cudaMemcpyToSymbolAsync(c_fco, scratch_dev, sizeof(u64) * 200, 0,
                            cudaMemcpyDeviceToDevice, 0);

    dim3 grid(W_IMG / 64, H_IMG / 32, B);
    dim3 block(32, 8);
    demosaick_kernel<<<grid, block>>>(img, out);
}

// round 17
// speedup vs baseline: 2.4886x; 1.0556x over previous
#include <cuda_runtime.h>
#include <cstdint>

// LearnableDemosaick R15 (= R14 + phase-decorrelated occupancy):
//  - 128-thread CTAs (4 warps), 32x32 output tile, __launch_bounds__(128, 7)
//    -> 7 CTAs/SM = 28 warps (7/SMSP, was 6) AND 7 independently-phased CTAs
//    (was 3) so prologue/epilogue phases of one CTA overlap compute of others.
//    Prior rounds showed the FMA2 pipe at only 52% duty with correlated
//    CTA phases; this buys stagger + latency hiding.
//  - TS=37 u64 row stride: lane-y bank pattern 10l mod 32 -> conflict-free
//    (same class as 69).
//  - otherwise R14: const-bank LDC.128 coefficients, dup-packed {v,v} tile,
//    parity-split dx, no-max softmax, staged float4 stores.

#define H_IMG 1024
#define W_IMG 1024
#define TS 37            // dup-tile row stride in u64 (conflict-free lane-y)
#define TILE_ROWS 36
#define TILE_COLS 36
#define SGS 36           // output stage row stride (floats)

typedef unsigned long long u64;

__constant__ u64 c_fco[25 * 8];      // [tap][k] = {sel_k, grn_k}
__device__ u64 d_fco_scratch[25 * 8];

__device__ __forceinline__ u64 fma2(u64 a, u64 b, u64 c) {
    u64 d;
    asm("fma.rn.f32x2 %0, %1, %2, %3;" : "=l"(d) : "l"(a), "l"(b), "l"(c));
    return d;
}
__device__ __forceinline__ u64 dup2(float v) {
    u64 d;
    asm("mov.b64 %0, {%1, %1};" : "=l"(d) : "f"(v));
    return d;
}
__device__ __forceinline__ u64 pack2(float lo, float hi) {
    u64 d;
    asm("mov.b64 %0, {%1, %2};" : "=l"(d) : "f"(lo), "f"(hi));
    return d;
}
__device__ __forceinline__ void unpack2(u64 p, float& lo, float& hi) {
    asm("mov.b64 {%0, %1}, %2;" : "=f"(lo), "=f"(hi) : "l"(p));
}

__global__ void pack_filters(const float* __restrict__ selF,
                             const float* __restrict__ grnF)
{
    int i = threadIdx.x;             // 200 entries
    if (i < 200) {
        int t = i >> 3, k = i & 7;   // tap, filter
        d_fco_scratch[i] = pack2(selF[k * 25 + t], grnF[k * 25 + t]);
    }
}

__global__ __launch_bounds__(128, 7)
void demosaick_kernel(const float* __restrict__ img,
                      float* __restrict__ out)
{
    __shared__ u64 tile[TILE_ROWS * TS];
    __shared__ float stage[32 * SGS];

    const int b  = blockIdx.z;
    const int y0 = blockIdx.y * 32;
    const int x0 = blockIdx.x * 32;
    const int tid = threadIdx.y * 32 + threadIdx.x;

    // Padded image tile, edge clamp, stored duplicated {v,v}.
    const float* imgB = img + (size_t)b * (H_IMG * W_IMG);
    for (int i = tid; i < TILE_ROWS * TILE_COLS; i += 128) {
        int r = i / TILE_COLS, c = i - r * TILE_COLS;
        int gy = y0 - 2 + r; gy = min(max(gy, 0), H_IMG - 1);
        int gx = x0 - 2 + c; gx = min(max(gx, 0), W_IMG - 1);
        tile[r * TS + c] = dup2(imgB[gy * W_IMG + gx]);
    }
    __syncthreads();

    const int ly = threadIdx.x;             // tile row (lane along y)
    const int y  = y0 + ly;
    const int cpar = (y + 1) & 1;           // compute-site x parity
    const int tcc = threadIdx.y * 8 + cpar; // window col = tcc + dx + 2*i

    u64 acc[8][4];
    #pragma unroll
    for (int k = 0; k < 8; k++)
        #pragma unroll
        for (int i = 0; i < 4; i++) acc[k][i] = 0ULL;

    const ulonglong2* fc128 = reinterpret_cast<const ulonglong2*>(c_fco);
    // fc128[tap*4 + j] = { {sel,grn}_{2j}, {sel,grn}_{2j+1} }

    #pragma unroll
    for (int dy = 0; dy < 5; dy++) {
        const u64* rb = &tile[(ly + dy) * TS + tcc];

        // even dx taps (0,2,4): offsets dx+2i even -> 6 pairs
        {
            u64 ve[6];
            #pragma unroll
            for (int c = 0; c < 6; c++) ve[c] = rb[2 * c];
            #pragma unroll
            for (int h = 0; h < 3; h++) {           // dx = 2h
                const int tap = dy * 5 + 2 * h;
                #pragma unroll
                for (int j = 0; j < 4; j++) {
                    const ulonglong2 cc = fc128[tap * 4 + j];  // LDC.128
                    #pragma unroll
                    for (int i = 0; i < 4; i++) {
                        acc[2 * j][i]     = fma2(cc.x, ve[h + i], acc[2 * j][i]);
                        acc[2 * j + 1][i] = fma2(cc.y, ve[h + i], acc[2 * j + 1][i]);
                    }
                }
            }
        }
        // odd dx taps (1,3): offsets odd -> 5 pairs
        {
            u64 vo[5];
            #pragma unroll
            for (int c = 0; c < 5; c++) vo[c] = rb[2 * c + 1];
            #pragma unroll
            for (int h = 0; h < 2; h++) {           // dx = 2h+1
                const int tap = dy * 5 + 2 * h + 1;
                #pragma unroll
                for (int j = 0; j < 4; j++) {
                    const ulonglong2 cc = fc128[tap * 4 + j];  // LDC.128
                    #pragma unroll
                    for (int i = 0; i < 4; i++) {
                        acc[2 * j][i]     = fma2(cc.x, vo[h + i], acc[2 * j][i]);
                        acc[2 * j + 1][i] = fma2(cc.y, vo[h + i], acc[2 * j + 1][i]);
                    }
                }
            }
        }
    }

    // Softmax blend -> stage (no max subtraction: sel values are O(0.1))
    #pragma unroll
    for (int i = 0; i < 4; i++) {
        float s[8], g[8];
        #pragma unroll
        for (int k = 0; k < 8; k++) unpack2(acc[k][i], s[k], g[k]);
        float wsum = 0.0f, gh = 0.0f;
        #pragma unroll
        for (int k = 0; k < 8; k++) {
            float e = __expf(s[k]);
            wsum += e;
            gh = fmaf(e, g[k], gh);
        }
        stage[ly * SGS + tcc + 2 * i] = __fdividef(gh, wsum);
    }

    // Passthrough green sites -> stage (low half of dup pair)
    const int gpar = y & 1;
    #pragma unroll
    for (int i = 0; i < 4; i++) {
        int c = threadIdx.y * 8 + gpar + 2 * i;
        float lo, hi;
        unpack2(tile[(ly + 2) * TS + c + 2], lo, hi);
        stage[ly * SGS + c] = lo;
    }
    __syncthreads();

    // Coalesced store: 32 rows x 8 float4 = 256 float4 per CTA
    #pragma unroll
    for (int f = tid; f < 256; f += 128) {
        int row = f >> 3, c4i = (f & 7) * 4;
        float4 val = *reinterpret_cast<const float4*>(&stage[row * SGS + c4i]);
        *reinterpret_cast<float4*>(
            &out[((size_t)b * H_IMG + y0 + row) * W_IMG + x0 + c4i]) = val;
    }
}

extern "C" void kernel_launch(void* const* d_in, const int* in_sizes, int n_in,
                              void* d_out, int out_size) {
    const float* img  = (const float*)d_in[0];
    const float* selF = (const float*)d_in[1];
    const float* grnF = (const float*)d_in[2];
    float* out = (float*)d_out;
    int B = in_sizes[0] / (H_IMG * W_IMG);

    pack_filters<<<1, 256>>>(selF, grnF);

    void* scratch_dev = nullptr;
    cudaGetSymbolAddress(&scratch_dev, d_fco_scratch);
    cudaMemcpyToSymbolAsync(c_fco, scratch_dev, sizeof(u64) * 200, 0,
                            cudaMemcpyDeviceToDevice, 0);

    dim3 grid(W_IMG / 32, H_IMG / 32, B);
    dim3 block(32, 4);
    demosaick_kernel<<<grid, block>>>(img, out);
}